// round 1
// baseline (speedup 1.0000x reference)
#include <cuda_runtime.h>
#include <cstdint>

#define N_NODES 200000
#define K1      500
#define EMB     128
#define HID     64
#define NCLS    7
#define BM      128
#define BK      32
#define NCHUNK  16      // ceil(500/32)
#define THREADS 256

// Shared layout (floats)
#define A_STRIDE   36
#define B_STRIDE   132
#define E_STRIDE   132
#define W1_STRIDE  68
#define H_STRIDE   68
#define OFF_A   0
#define OFF_B   (OFF_A + 2*128*A_STRIDE)
#define OFF_E   (OFF_B + 2*32*B_STRIDE)
#define OFF_W1  (OFF_E + 128*E_STRIDE)
#define OFF_H   (OFF_W1 + 128*W1_STRIDE)
#define OFF_W2  (OFF_H + 128*H_STRIDE)
#define SMEM_FLOATS (OFF_W2 + 448)
#define SMEM_BYTES  (SMEM_FLOATS * 4)

__device__ __forceinline__ uint32_t f2tf32(float x) {
    uint32_t r;
    asm("cvt.rna.tf32.f32 %0, %1;" : "=r"(r) : "f"(x));
    return r;
}

__device__ __forceinline__ void mma_tf32(float c[4], const uint32_t a[4], const uint32_t b[2]) {
    asm volatile(
        "mma.sync.aligned.m16n8k8.row.col.f32.tf32.tf32.f32 "
        "{%0,%1,%2,%3},{%4,%5,%6,%7},{%8,%9},{%0,%1,%2,%3};"
        : "+f"(c[0]), "+f"(c[1]), "+f"(c[2]), "+f"(c[3])
        : "r"(a[0]), "r"(a[1]), "r"(a[2]), "r"(a[3]), "r"(b[0]), "r"(b[1]));
}

__device__ __forceinline__ void cp16(uint32_t saddr, const void* gaddr, bool pred) {
    int sz = pred ? 16 : 0;
    asm volatile("cp.async.cg.shared.global [%0], [%1], 16, %2;"
                 :: "r"(saddr), "l"(gaddr), "r"(sz));
}

__device__ __forceinline__ void load_chunk(
    int c, int buf, int tid, int row0,
    const float* __restrict__ features, const float* __restrict__ W_emb,
    uint32_t sA, uint32_t sB)
{
    // A tile: 128 rows x 32 k = 1024 float4
    #pragma unroll
    for (int i = 0; i < 4; i++) {
        int v = tid + i * THREADS;
        int r = v >> 3;
        int kv = (v & 7) * 4;
        int gr = row0 + r;
        int gk = c * BK + kv;
        bool p = (gr < N_NODES) && (gk + 4 <= K1);
        const float* src = features + (p ? ((size_t)gr * K1 + gk) : 0);
        cp16(sA + (uint32_t)(((buf * 128 + r) * A_STRIDE + kv) * 4), src, p);
    }
    // B tile: 32 k x 128 n = 1024 float4
    #pragma unroll
    for (int i = 0; i < 4; i++) {
        int v = tid + i * THREADS;
        int r = v >> 5;
        int nv = (v & 31) * 4;
        int gk = c * BK + r;
        bool p = (gk < K1);
        const float* src = W_emb + (p ? ((size_t)gk * EMB + nv) : 0);
        cp16(sB + (uint32_t)(((buf * 32 + r) * B_STRIDE + nv) * 4), src, p);
    }
}

__global__ void __launch_bounds__(THREADS, 1)
policy_fused_kernel(
    const float* __restrict__ features,
    const float* __restrict__ W_emb,  const float* __restrict__ b_emb,
    const float* __restrict__ W_rt1,  const float* __restrict__ b_rt1,
    const float* __restrict__ W_rt2,  const float* __restrict__ b_rt2,
    float* __restrict__ out)
{
    extern __shared__ float sm[];
    float* A_s   = sm + OFF_A;
    float* B_s   = sm + OFF_B;
    float* emb_s = sm + OFF_E;
    float* W1_s  = sm + OFF_W1;
    float* h_s   = sm + OFF_H;
    float* W2_s  = sm + OFF_W2;

    const int tid  = threadIdx.x;
    const int row0 = blockIdx.x * BM;
    const uint32_t sA = (uint32_t)__cvta_generic_to_shared(A_s);
    const uint32_t sB = (uint32_t)__cvta_generic_to_shared(B_s);

    const int warp = tid >> 5, lane = tid & 31;
    const int grp = lane >> 2, tig = lane & 3;
    const int wm = (warp >> 2) * 64;     // warp row base (0 or 64)
    const int wn = (warp & 3) * 32;      // warp col base for stage 1

    // ---------------- Stage 1: emb = relu(X @ W_emb + b_emb) ----------------
    float acc[4][4][4];
    #pragma unroll
    for (int mt = 0; mt < 4; mt++)
        #pragma unroll
        for (int nt = 0; nt < 4; nt++)
            #pragma unroll
            for (int e = 0; e < 4; e++) acc[mt][nt][e] = 0.0f;

    load_chunk(0, 0, tid, row0, features, W_emb, sA, sB);
    asm volatile("cp.async.commit_group;");

    for (int c = 0; c < NCHUNK; c++) {
        const int buf = c & 1;
        if (c + 1 < NCHUNK) {
            load_chunk(c + 1, buf ^ 1, tid, row0, features, W_emb, sA, sB);
            asm volatile("cp.async.commit_group;");
            asm volatile("cp.async.wait_group 1;");
        } else {
            asm volatile("cp.async.wait_group 0;");
        }
        __syncthreads();

        const float* At = A_s + buf * (128 * A_STRIDE);
        const float* Bt = B_s + buf * (32 * B_STRIDE);

        #pragma unroll
        for (int ks = 0; ks < 4; ks++) {
            const int k = ks * 8 + tig;
            uint32_t a[4][4], b[4][2];
            #pragma unroll
            for (int mt = 0; mt < 4; mt++) {
                const int r = wm + mt * 16 + grp;
                a[mt][0] = f2tf32(At[r * A_STRIDE + k]);
                a[mt][1] = f2tf32(At[(r + 8) * A_STRIDE + k]);
                a[mt][2] = f2tf32(At[r * A_STRIDE + k + 4]);
                a[mt][3] = f2tf32(At[(r + 8) * A_STRIDE + k + 4]);
            }
            #pragma unroll
            for (int nt = 0; nt < 4; nt++) {
                const int col = wn + nt * 8 + grp;
                b[nt][0] = f2tf32(Bt[k * B_STRIDE + col]);
                b[nt][1] = f2tf32(Bt[(k + 4) * B_STRIDE + col]);
            }
            #pragma unroll
            for (int mt = 0; mt < 4; mt++)
                #pragma unroll
                for (int nt = 0; nt < 4; nt++)
                    mma_tf32(acc[mt][nt], a[mt], b[nt]);
        }
        __syncthreads();
    }

    // Epilogue 1: bias + relu -> emb_s
    #pragma unroll
    for (int mt = 0; mt < 4; mt++) {
        #pragma unroll
        for (int nt = 0; nt < 4; nt++) {
            const int r = wm + mt * 16 + grp;
            const int col = wn + nt * 8 + tig * 2;
            const float bb0 = b_emb[col], bb1 = b_emb[col + 1];
            emb_s[r * E_STRIDE + col]           = fmaxf(acc[mt][nt][0] + bb0, 0.0f);
            emb_s[r * E_STRIDE + col + 1]       = fmaxf(acc[mt][nt][1] + bb1, 0.0f);
            emb_s[(r + 8) * E_STRIDE + col]     = fmaxf(acc[mt][nt][2] + bb0, 0.0f);
            emb_s[(r + 8) * E_STRIDE + col + 1] = fmaxf(acc[mt][nt][3] + bb1, 0.0f);
        }
    }

    // Load W_rt1 / W_rt2 into shared (L2-resident, small)
    for (int i = tid; i < (128 * 64) / 4; i += THREADS) {
        int r = i >> 4;            // 16 float4 per row of 64
        int nv = (i & 15) * 4;
        float4 w = *(const float4*)(W_rt1 + r * 64 + nv);
        *(float4*)(W1_s + r * W1_STRIDE + nv) = w;
    }
    for (int i = tid; i < HID * NCLS; i += THREADS) W2_s[i] = W_rt2[i];
    __syncthreads();

    // ---------------- Stage 2: h = relu(emb @ W_rt1 + b_rt1) ----------------
    const int wn2 = (warp & 3) * 16;
    float acc2[4][2][4];
    #pragma unroll
    for (int mt = 0; mt < 4; mt++)
        #pragma unroll
        for (int nt = 0; nt < 2; nt++)
            #pragma unroll
            for (int e = 0; e < 4; e++) acc2[mt][nt][e] = 0.0f;

    #pragma unroll
    for (int ks = 0; ks < 16; ks++) {
        const int k = ks * 8 + tig;
        uint32_t a[4][4], b[2][2];
        #pragma unroll
        for (int mt = 0; mt < 4; mt++) {
            const int r = wm + mt * 16 + grp;
            a[mt][0] = f2tf32(emb_s[r * E_STRIDE + k]);
            a[mt][1] = f2tf32(emb_s[(r + 8) * E_STRIDE + k]);
            a[mt][2] = f2tf32(emb_s[r * E_STRIDE + k + 4]);
            a[mt][3] = f2tf32(emb_s[(r + 8) * E_STRIDE + k + 4]);
        }
        #pragma unroll
        for (int nt = 0; nt < 2; nt++) {
            const int col = wn2 + nt * 8 + grp;
            b[nt][0] = f2tf32(W1_s[k * W1_STRIDE + col]);
            b[nt][1] = f2tf32(W1_s[(k + 4) * W1_STRIDE + col]);
        }
        #pragma unroll
        for (int mt = 0; mt < 4; mt++)
            #pragma unroll
            for (int nt = 0; nt < 2; nt++)
                mma_tf32(acc2[mt][nt], a[mt], b[nt]);
    }

    // Epilogue 2: bias + relu -> h_s
    #pragma unroll
    for (int mt = 0; mt < 4; mt++) {
        #pragma unroll
        for (int nt = 0; nt < 2; nt++) {
            const int r = wm + mt * 16 + grp;
            const int col = wn2 + nt * 8 + tig * 2;
            const float bb0 = b_rt1[col], bb1 = b_rt1[col + 1];
            h_s[r * H_STRIDE + col]           = fmaxf(acc2[mt][nt][0] + bb0, 0.0f);
            h_s[r * H_STRIDE + col + 1]       = fmaxf(acc2[mt][nt][1] + bb1, 0.0f);
            h_s[(r + 8) * H_STRIDE + col]     = fmaxf(acc2[mt][nt][2] + bb0, 0.0f);
            h_s[(r + 8) * H_STRIDE + col + 1] = fmaxf(acc2[mt][nt][3] + bb1, 0.0f);
        }
    }
    __syncthreads();

    // ---------------- Stage 3: out = h @ W_rt2 + b_rt2 (scalar fp32) --------
    for (int idx = tid; idx < BM * NCLS; idx += THREADS) {
        const int r = idx / NCLS;
        const int col = idx - r * NCLS;
        float s = b_rt2[col];
        #pragma unroll
        for (int j = 0; j < HID; j++)
            s = fmaf(h_s[r * H_STRIDE + j], W2_s[j * NCLS + col], s);
        const int gr = row0 + r;
        if (gr < N_NODES) out[(size_t)gr * NCLS + col] = s;
    }
}

extern "C" void kernel_launch(void* const* d_in, const int* in_sizes, int n_in,
                              void* d_out, int out_size) {
    // inputs: [0] adj (unused), [1] features, [2] W_emb, [3] b_emb,
    //         [4] W_rt1, [5] b_rt1, [6] W_rt2, [7] b_rt2
    const float* features = (const float*)d_in[1];
    const float* W_emb    = (const float*)d_in[2];
    const float* b_emb    = (const float*)d_in[3];
    const float* W_rt1    = (const float*)d_in[4];
    const float* b_rt1    = (const float*)d_in[5];
    const float* W_rt2    = (const float*)d_in[6];
    const float* b_rt2    = (const float*)d_in[7];
    float* out = (float*)d_out;

    cudaFuncSetAttribute(policy_fused_kernel,
                         cudaFuncAttributeMaxDynamicSharedMemorySize, SMEM_BYTES);

    const int grid = (N_NODES + BM - 1) / BM;  // 1563
    policy_fused_kernel<<<grid, THREADS, SMEM_BYTES>>>(
        features, W_emb, b_emb, W_rt1, b_rt1, W_rt2, b_rt2, out);
}

// round 3
// speedup vs baseline: 1.9603x; 1.9603x over previous
#include <cuda_runtime.h>
#include <cuda_fp16.h>
#include <cstdint>

#define N_NODES 200000
#define K1      500
#define KK      256        // K1 padded to 512 halves -> 256 half2
#define EMB     128
#define HID     64
#define NCLS    7
#define BM      128
#define NCHUNK  16
#define THREADS 256

// strides in uint32 units (bank-conflict-free)
#define A_STR   20         // A tile row: 16 half2 + 4 pad
#define B_STR   136        // B tile row: 128 half2 + 8 pad
#define E_STR   68         // emb row: 64 half2 + 4 pad   (also h fp32 row: 64 + 4)
#define W1_STR  72         // W1 row: 64 half2 + 8 pad

// byte offsets in dynamic smem
#define OFF_BEMB 0
#define OFF_BRT1 512
#define OFF_BRT2 768
#define OFF_W2   832                       // 448 floats
#define OFF_A0   2688                      // 128*A_STR*4 = 10240
#define OFF_A1   (OFF_A0 + 10240)
#define OFF_B0   (OFF_A1 + 10240)          // 16*B_STR*4 = 8704
#define OFF_B1   (OFF_B0 + 8704)
#define OFF_E    (OFF_B1 + 8704)           // 128*E_STR*4 = 34816 (emb fp16 / later h fp32)
#define OFF_W1   (OFF_E + 34816)           // 64*W1_STR*4 = 18432
#define SMEM_BYTES (OFF_W1 + 18432)        // 93824 -> 2 CTAs/SM

// prep-packed weights: half2 pairs along k
__device__ uint32_t g_WembP[KK * EMB];     // [kk][n]
__device__ uint32_t g_W1P[(EMB/2) * HID];  // [kk][n]

__device__ __forceinline__ uint32_t pack2(float a, float b) {
    __half2 h = __floats2half2_rn(a, b);
    return *reinterpret_cast<uint32_t*>(&h);
}
__device__ __forceinline__ void cp16(uint32_t dst, const void* src, bool p) {
    int sz = p ? 16 : 0;
    asm volatile("cp.async.cg.shared.global [%0], [%1], 16, %2;"
                 :: "r"(dst), "l"(src), "r"(sz));
}
__device__ __forceinline__ void mma16(float c[4], const uint32_t a[4], const uint32_t b[2]) {
    asm volatile(
        "mma.sync.aligned.m16n8k16.row.col.f32.f16.f16.f32 "
        "{%0,%1,%2,%3},{%4,%5,%6,%7},{%8,%9},{%0,%1,%2,%3};"
        : "+f"(c[0]), "+f"(c[1]), "+f"(c[2]), "+f"(c[3])
        : "r"(a[0]), "r"(a[1]), "r"(a[2]), "r"(a[3]), "r"(b[0]), "r"(b[1]));
}

// ---------------- prep: pack weights as half2-k-pairs ----------------
__global__ void prep_kernel(const float* __restrict__ W_emb,
                            const float* __restrict__ W_rt1) {
    int i = blockIdx.x * blockDim.x + threadIdx.x;
    const int T1 = KK * EMB;
    if (i < T1) {
        int kk = i >> 7, n = i & 127;
        float w0 = (2 * kk     < K1) ? W_emb[(size_t)(2 * kk) * EMB + n]     : 0.0f;
        float w1 = (2 * kk + 1 < K1) ? W_emb[(size_t)(2 * kk + 1) * EMB + n] : 0.0f;
        g_WembP[i] = pack2(w0, w1);
    } else if (i < T1 + (EMB/2) * HID) {
        int j = i - T1; int kk = j >> 6, n = j & 63;
        g_W1P[j] = pack2(W_rt1[(2 * kk) * HID + n], W_rt1[(2 * kk + 1) * HID + n]);
    }
}

// ---------------- main fused kernel ----------------
__global__ void __launch_bounds__(THREADS, 2)
policy_fp16_kernel(const float* __restrict__ features,
                   const float* __restrict__ b_emb,
                   const float* __restrict__ b_rt1,
                   const float* __restrict__ b_rt2,
                   const float* __restrict__ W_rt2,
                   float* __restrict__ out)
{
    extern __shared__ char smem[];
    const int tid  = threadIdx.x;
    const int warp = tid >> 5, lane = tid & 31;
    const int grp  = lane >> 2, tig = lane & 3;
    const int wm   = (warp >> 2) * 64;
    const int wn   = (warp & 3) * 32;
    const int row0 = blockIdx.x * BM;

    float*    bemb_s = (float*)(smem + OFF_BEMB);
    float*    brt1_s = (float*)(smem + OFF_BRT1);
    float*    brt2_s = (float*)(smem + OFF_BRT2);
    float*    w2_s   = (float*)(smem + OFF_W2);
    uint32_t* A0s    = (uint32_t*)(smem + OFF_A0);
    uint32_t* A1s    = (uint32_t*)(smem + OFF_A1);
    uint32_t* B0s    = (uint32_t*)(smem + OFF_B0);
    uint32_t* B1s    = (uint32_t*)(smem + OFF_B1);
    uint32_t* Es     = (uint32_t*)(smem + OFF_E);
    uint32_t* W1s    = (uint32_t*)(smem + OFF_W1);
    const uint32_t sbase = (uint32_t)__cvta_generic_to_shared(smem);

    // small constants
    for (int i = tid; i < EMB;        i += THREADS) bemb_s[i] = b_emb[i];
    for (int i = tid; i < HID;        i += THREADS) brt1_s[i] = b_rt1[i];
    for (int i = tid; i < NCLS;       i += THREADS) brt2_s[i] = b_rt2[i];
    for (int i = tid; i < HID * NCLS; i += THREADS) w2_s[i]   = W_rt2[i];

    // W1 -> smem (64 rows x 64 u32), cp.async
    #pragma unroll
    for (int i = 0; i < 4; i++) {
        int v = tid + i * THREADS;            // 0..1023
        int kk = v >> 4, n4 = (v & 15) * 4;
        cp16(sbase + OFF_W1 + (uint32_t)((kk * W1_STR + n4) * 4),
             g_W1P + kk * HID + n4, true);
    }

    // helpers as lambdas
    auto ldgA = [&](int c, uint4* pf) {
        #pragma unroll
        for (int i = 0; i < 4; i++) {
            int v = tid + i * THREADS;
            int r = v >> 3, k4 = (v & 7) * 4;
            int gr = row0 + r, gk = c * 32 + k4;
            bool p = (gr < N_NODES) && (gk + 4 <= K1);
            if (p) pf[i] = *(const uint4*)(features + (size_t)gr * K1 + gk);
            else   pf[i] = make_uint4(0, 0, 0, 0);
        }
    };
    auto stsA = [&](const uint4* pf, uint32_t* Ab) {
        #pragma unroll
        for (int i = 0; i < 4; i++) {
            int v = tid + i * THREADS;
            int r = v >> 3, k2 = (v & 7) * 2;
            uint2 w;
            w.x = pack2(__uint_as_float(pf[i].x), __uint_as_float(pf[i].y));
            w.y = pack2(__uint_as_float(pf[i].z), __uint_as_float(pf[i].w));
            *(uint2*)(Ab + r * A_STR + k2) = w;
        }
    };
    auto cpB = [&](int c, uint32_t offB) {
        #pragma unroll
        for (int i = 0; i < 2; i++) {
            int v = tid + i * THREADS;        // 0..511
            int kk = v >> 5, n4 = (v & 31) * 4;
            cp16(sbase + offB + (uint32_t)((kk * B_STR + n4) * 4),
                 g_WembP + (c * 16 + kk) * EMB + n4, true);
        }
    };

    // -------- stage 1 prologue --------
    cpB(0, OFF_B0);
    asm volatile("cp.async.commit_group;");
    uint4 pf[4];
    ldgA(0, pf);
    stsA(pf, A0s);
    ldgA(1, pf);
    asm volatile("cp.async.wait_group 0;");
    __syncthreads();

    float acc[4][4][4];
    #pragma unroll
    for (int mt = 0; mt < 4; mt++)
        #pragma unroll
        for (int nt = 0; nt < 4; nt++)
            #pragma unroll
            for (int e = 0; e < 4; e++) acc[mt][nt][e] = 0.0f;

    // -------- stage 1 main loop --------
    for (int c = 0; c < NCHUNK; c++) {
        const uint32_t* Ab = (c & 1) ? A1s : A0s;
        const uint32_t* Bb = (c & 1) ? B1s : B0s;
        if (c + 1 < NCHUNK) {
            cpB(c + 1, (c & 1) ? OFF_B0 : OFF_B1);
            asm volatile("cp.async.commit_group;");
        }

        #pragma unroll
        for (int s = 0; s < 2; s++) {
            uint32_t a[4][4], b[4][2];
            #pragma unroll
            for (int mt = 0; mt < 4; mt++) {
                const int r = wm + mt * 16 + grp;
                a[mt][0] = Ab[r * A_STR + s * 8 + tig];
                a[mt][1] = Ab[(r + 8) * A_STR + s * 8 + tig];
                a[mt][2] = Ab[r * A_STR + s * 8 + tig + 4];
                a[mt][3] = Ab[(r + 8) * A_STR + s * 8 + tig + 4];
            }
            #pragma unroll
            for (int nt = 0; nt < 4; nt++) {
                const int col = wn + nt * 8 + grp;
                b[nt][0] = Bb[(s * 8 + tig) * B_STR + col];
                b[nt][1] = Bb[(s * 8 + tig + 4) * B_STR + col];
            }
            #pragma unroll
            for (int mt = 0; mt < 4; mt++)
                #pragma unroll
                for (int nt = 0; nt < 4; nt++)
                    mma16(acc[mt][nt], a[mt], b[nt]);
        }

        if (c + 1 < NCHUNK) {
            stsA(pf, (c & 1) ? A0s : A1s);
            if (c + 2 < NCHUNK) ldgA(c + 2, pf);
            asm volatile("cp.async.wait_group 0;");
            __syncthreads();
        }
    }
    __syncthreads();

    // -------- epilogue 1: emb = relu(acc + b_emb) as half2 --------
    #pragma unroll
    for (int mt = 0; mt < 4; mt++) {
        #pragma unroll
        for (int nt = 0; nt < 4; nt++) {
            const int r    = wm + mt * 16 + grp;
            const int col  = wn + nt * 8 + tig * 2;
            const int colh = (wn + nt * 8) / 2 + tig;
            const float b0 = bemb_s[col], b1 = bemb_s[col + 1];
            Es[r * E_STR + colh] =
                pack2(fmaxf(acc[mt][nt][0] + b0, 0.0f), fmaxf(acc[mt][nt][1] + b1, 0.0f));
            Es[(r + 8) * E_STR + colh] =
                pack2(fmaxf(acc[mt][nt][2] + b0, 0.0f), fmaxf(acc[mt][nt][3] + b1, 0.0f));
        }
    }
    __syncthreads();

    // -------- stage 2: h = relu(emb @ W_rt1 + b_rt1) --------
    const int wn2 = (warp & 3) * 16;
    float acc2[4][2][4];
    #pragma unroll
    for (int mt = 0; mt < 4; mt++)
        #pragma unroll
        for (int nt = 0; nt < 2; nt++)
            #pragma unroll
            for (int e = 0; e < 4; e++) acc2[mt][nt][e] = 0.0f;

    #pragma unroll
    for (int s = 0; s < 8; s++) {
        uint32_t a[4][4], b[2][2];
        #pragma unroll
        for (int mt = 0; mt < 4; mt++) {
            const int r = wm + mt * 16 + grp;
            a[mt][0] = Es[r * E_STR + s * 8 + tig];
            a[mt][1] = Es[(r + 8) * E_STR + s * 8 + tig];
            a[mt][2] = Es[r * E_STR + s * 8 + tig + 4];
            a[mt][3] = Es[(r + 8) * E_STR + s * 8 + tig + 4];
        }
        #pragma unroll
        for (int nt = 0; nt < 2; nt++) {
            const int col = wn2 + nt * 8 + grp;
            b[nt][0] = W1s[(s * 8 + tig) * W1_STR + col];
            b[nt][1] = W1s[(s * 8 + tig + 4) * W1_STR + col];
        }
        #pragma unroll
        for (int mt = 0; mt < 4; mt++)
            #pragma unroll
            for (int nt = 0; nt < 2; nt++)
                mma16(acc2[mt][nt], a[mt], b[nt]);
    }
    __syncthreads();   // all reads of Es done; reuse region for h (fp32)

    float* hs = (float*)(smem + OFF_E);
    #pragma unroll
    for (int mt = 0; mt < 4; mt++) {
        #pragma unroll
        for (int nt = 0; nt < 2; nt++) {
            const int r   = wm + mt * 16 + grp;
            const int col = wn2 + nt * 8 + tig * 2;
            const float b0 = brt1_s[col], b1 = brt1_s[col + 1];
            float2 v0 = make_float2(fmaxf(acc2[mt][nt][0] + b0, 0.0f),
                                    fmaxf(acc2[mt][nt][1] + b1, 0.0f));
            float2 v1 = make_float2(fmaxf(acc2[mt][nt][2] + b0, 0.0f),
                                    fmaxf(acc2[mt][nt][3] + b1, 0.0f));
            *(float2*)(hs + r * E_STR + col)       = v0;
            *(float2*)(hs + (r + 8) * E_STR + col) = v1;
        }
    }
    __syncthreads();

    // -------- stage 3: out = h @ W_rt2 + b_rt2 (scalar fp32) --------
    if (warp < 4) {
        const int r  = warp * 32 + lane;
        const int gr = row0 + r;
        float o[NCLS];
        #pragma unroll
        for (int cc = 0; cc < NCLS; cc++) o[cc] = brt2_s[cc];
        #pragma unroll
        for (int k4 = 0; k4 < HID; k4 += 4) {
            float4 h4 = *(const float4*)(hs + r * E_STR + k4);
            const float hh[4] = {h4.x, h4.y, h4.z, h4.w};
            #pragma unroll
            for (int j = 0; j < 4; j++)
                #pragma unroll
                for (int cc = 0; cc < NCLS; cc++)
                    o[cc] = fmaf(hh[j], w2_s[(k4 + j) * NCLS + cc], o[cc]);
        }
        if (gr < N_NODES) {
            #pragma unroll
            for (int cc = 0; cc < NCLS; cc++)
                out[(size_t)gr * NCLS + cc] = o[cc];
        }
    }
}

extern "C" void kernel_launch(void* const* d_in, const int* in_sizes, int n_in,
                              void* d_out, int out_size) {
    // [0] adj (unused), [1] features, [2] W_emb, [3] b_emb,
    // [4] W_rt1, [5] b_rt1, [6] W_rt2, [7] b_rt2
    const float* features = (const float*)d_in[1];
    const float* W_emb    = (const float*)d_in[2];
    const float* b_emb    = (const float*)d_in[3];
    const float* W_rt1    = (const float*)d_in[4];
    const float* b_rt1    = (const float*)d_in[5];
    const float* W_rt2    = (const float*)d_in[6];
    const float* b_rt2    = (const float*)d_in[7];
    float* out = (float*)d_out;

    const int prep_elems = KK * EMB + (EMB / 2) * HID;
    prep_kernel<<<(prep_elems + 255) / 256, 256>>>(W_emb, W_rt1);

    cudaFuncSetAttribute(policy_fp16_kernel,
                         cudaFuncAttributeMaxDynamicSharedMemorySize, SMEM_BYTES);
    const int grid = (N_NODES + BM - 1) / BM;   // 1563
    policy_fp16_kernel<<<grid, THREADS, SMEM_BYTES>>>(
        features, b_emb, b_rt1, b_rt2, W_rt2, out);
}